// round 1
// baseline (speedup 1.0000x reference)
#include <cuda_runtime.h>
#include <math.h>

#define BN 16
#define HH 288
#define WW 384
#define NPTS (HH*WW)          // 110592
#define NITER 5
#define BPB 27                // blocks per batch
#define TPB 256
#define STRIDE (BPB*TPB)      // 6912 = 18*384 -> px loop-invariant

// persistent per-launch state (device globals: no allocation)
__device__ double g_acc[BN][27];
__device__ float  g_R[BN][9];
__device__ float  g_t[BN][3];

__global__ void init_kernel() {
    int i = threadIdx.x;
    if (i < BN * 27) ((double*)g_acc)[i] = 0.0;
    if (i < BN) {
        g_R[i][0] = 1.f; g_R[i][1] = 0.f; g_R[i][2] = 0.f;
        g_R[i][3] = 0.f; g_R[i][4] = 1.f; g_R[i][5] = 0.f;
        g_R[i][6] = 0.f; g_R[i][7] = 0.f; g_R[i][8] = 1.f;
        g_t[i][0] = 0.f; g_t[i][1] = 0.f; g_t[i][2] = 0.f;
    }
}

// Accumulate JTJ (21 upper-tri) and JTr (6) per batch.
__global__ void __launch_bounds__(TPB) reduce_kernel(
    const float* __restrict__ pts,
    const float* __restrict__ conf,
    const float* __restrict__ Kin)
{
    const int b = blockIdx.y;
    const float fx = Kin[b * 9 + 0], cx = Kin[b * 9 + 2];
    const float fy = Kin[b * 9 + 4], cy = Kin[b * 9 + 5];
    const float R00 = g_R[b][0], R01 = g_R[b][1], R02 = g_R[b][2];
    const float R10 = g_R[b][3], R11 = g_R[b][4], R12 = g_R[b][5];
    const float R20 = g_R[b][6], R21 = g_R[b][7], R22 = g_R[b][8];
    const float t0 = g_t[b][0], t1 = g_t[b][1], t2 = g_t[b][2];

    // delta = 0.1*sqrt(var(px)+var(py)) over the fixed pixel grid (constant)
    const float delta = 0.1f * sqrtf(((float)WW * (float)WW - 1.f) / 12.f +
                                     ((float)HH * (float)HH - 1.f) / 12.f);

    const int base = blockIdx.x * TPB + (int)threadIdx.x;     // 0..6911
    const float px = (float)(base % WW);
    const int   py0 = base / WW;                              // py = py0 + 18*k

    const float* __restrict__ P  = pts  + (size_t)b * NPTS * 3 + (size_t)3 * base;
    const float* __restrict__ Cw = conf + (size_t)b * NPTS + base;

    float acc[27];
#pragma unroll
    for (int k = 0; k < 27; k++) acc[k] = 0.f;

#pragma unroll 4
    for (int k = 0; k < NPTS / STRIDE; k++) {               // exactly 16 iters
        const float p0 = P[0], p1 = P[1], p2 = P[2];
        const float w  = Cw[0];
        P  += 3 * STRIDE;
        Cw += STRIDE;
        const float py = (float)(py0 + (HH / (NPTS / STRIDE)) * k); // +18*k

        const float X  = fmaf(R00, p0, fmaf(R01, p1, fmaf(R02, p2, t0)));
        const float Y  = fmaf(R10, p0, fmaf(R11, p1, fmaf(R12, p2, t1)));
        const float Zc = fmaf(R20, p0, fmaf(R21, p1, fmaf(R22, p2, t2)));
        const float z  = fmaxf(Zc, 0.01f);
        const float iz = 1.0f / z;

        const float rx = fx * X * iz + cx - px;
        const float ry = fy * Y * iz + cy - py;
        const float wrx = w * rx, wry = w * ry;
        const float rn  = sqrtf(wrx * wrx + wry * wry);
        const float rob = sqrtf(fminf(1.f, delta / fmaxf(rn, 1e-8f)));
        const float wt  = w * rob;
        const float s   = wt * wt;

        const float a  = fx * iz;
        const float bb = -fx * X * iz * iz;
        const float c  = fy * iz;
        const float d  = -fy * Y * iz * iz;

        // J row0 = [a, 0, bb,  bb*Y,       a*Zc-bb*X, -a*Y]
        // J row1 = [0, c, d,  -c*Zc+d*Y,  -d*X,        c*X]   (Zc unclamped in skew)
        float J0[6] = { a, 0.f, bb, bb * Y, a * Zc - bb * X, -a * Y };
        float J1[6] = { 0.f, c, d, -c * Zc + d * Y, -d * X, c * X };

        int off = 0;
#pragma unroll
        for (int i = 0; i < 6; i++) {
#pragma unroll
            for (int j = i; j < 6; j++)
                acc[off++] = fmaf(s, J0[i] * J0[j] + J1[i] * J1[j], acc[off]);
        }
#pragma unroll
        for (int i = 0; i < 6; i++)
            acc[21 + i] = fmaf(s, rx * J0[i] + ry * J1[i], acc[21 + i]);
    }

    // warp reduce each of 27 sums
#pragma unroll
    for (int k = 0; k < 27; k++) {
        float v = acc[k];
#pragma unroll
        for (int o = 16; o > 0; o >>= 1) v += __shfl_down_sync(0xffffffffu, v, o);
        acc[k] = v;
    }
    __shared__ float sm[TPB / 32][27];
    const int wid = threadIdx.x >> 5, lane = threadIdx.x & 31;
    if (lane == 0) {
#pragma unroll
        for (int k = 0; k < 27; k++) sm[wid][k] = acc[k];
    }
    __syncthreads();
    if (threadIdx.x < 27) {
        double v = 0.0;
#pragma unroll
        for (int wv = 0; wv < TPB / 32; wv++) v += (double)sm[wv][threadIdx.x];
        atomicAdd(&g_acc[b][threadIdx.x], v);
    }
}

// Per-batch 6x6 LM solve + SE(3) update; re-zero accumulators.
__global__ void solve_kernel() {
    const int b = threadIdx.x;
    if (b >= BN) return;

    double m[27];
#pragma unroll
    for (int k = 0; k < 27; k++) m[k] = g_acc[b][k];

    double A[6][7];
    {
        int off = 0;
        for (int i = 0; i < 6; i++)
            for (int j = i; j < 6; j++) { A[i][j] = m[off]; A[j][i] = m[off]; off++; }
    }
    const double tr = A[0][0] + A[1][1] + A[2][2] + A[3][3] + A[4][4] + A[5][5];
    const double damp = 1e-4 * tr / 6.0 + 1e-6;
    for (int i = 0; i < 6; i++) { A[i][i] += damp; A[i][6] = -m[21 + i]; }

    // Gaussian elimination with partial pivoting
    for (int col = 0; col < 6; col++) {
        int piv = col; double best = fabs(A[col][col]);
        for (int r = col + 1; r < 6; r++) {
            double v = fabs(A[r][col]);
            if (v > best) { best = v; piv = r; }
        }
        if (piv != col)
            for (int q = col; q < 7; q++) { double tmp = A[col][q]; A[col][q] = A[piv][q]; A[piv][q] = tmp; }
        const double inv = 1.0 / A[col][col];
        for (int r = col + 1; r < 6; r++) {
            const double f = A[r][col] * inv;
            for (int q = col; q < 7; q++) A[r][q] -= f * A[col][q];
        }
    }
    double dx[6];
    for (int i = 5; i >= 0; i--) {
        double s = A[i][6];
        for (int j = i + 1; j < 6; j++) s -= A[i][j] * dx[j];
        dx[i] = s / A[i][i];
    }

    g_t[b][0] += (float)dx[0];
    g_t[b][1] += (float)dx[1];
    g_t[b][2] += (float)dx[2];

    // R = exp_so3(dx[3:]) @ R
    const double wx = dx[3], wy = dx[4], wz = dx[5];
    double th = sqrt(wx * wx + wy * wy + wz * wz);
    if (th < 1e-8) th = 1e-8;
    const double ux = wx / th, uy = wy / th, uz = wz / th;
    const double st = sin(th), ct = cos(th), vt = 1.0 - ct;
    double E[3][3] = {
        { ct + vt * ux * ux,      vt * ux * uy - st * uz, vt * ux * uz + st * uy },
        { vt * uy * ux + st * uz, ct + vt * uy * uy,      vt * uy * uz - st * ux },
        { vt * uz * ux - st * uy, vt * uz * uy + st * ux, ct + vt * uz * uz }
    };
    double Ro[3][3];
    for (int i = 0; i < 3; i++)
        for (int j = 0; j < 3; j++) Ro[i][j] = (double)g_R[b][i * 3 + j];
    for (int i = 0; i < 3; i++)
        for (int j = 0; j < 3; j++)
            g_R[b][i * 3 + j] = (float)(E[i][0] * Ro[0][j] + E[i][1] * Ro[1][j] + E[i][2] * Ro[2][j]);

#pragma unroll
    for (int k = 0; k < 27; k++) g_acc[b][k] = 0.0;
}

// Relative-pose losses vs ground truth. Single thread (B=16, trivial).
__global__ void final_kernel(const float* __restrict__ pose, float* __restrict__ out) {
    if (threadIdx.x != 0 || blockIdx.x != 0) return;

    double R0p[3][3], t0p[3], R0g[3][3], t0g[3];
    for (int i = 0; i < 3; i++) {
        for (int j = 0; j < 3; j++) {
            R0p[i][j] = (double)g_R[0][i * 3 + j];
            R0g[i][j] = (double)pose[0 * 16 + i * 4 + j];
        }
        t0p[i] = (double)g_t[0][i];
        t0g[i] = (double)pose[0 * 16 + i * 4 + 3];
    }

    const double hi = (double)(float)(1.0 - 1e-7);
    const double lo = (double)(float)(-1.0 + 1e-7);

    double rot_sum = 0.0, trans_sum = 0.0;
    for (int b = 0; b < BN; b++) {
        double Rbp[3][3], tbp[3], Rbg[3][3], tbg[3];
        for (int i = 0; i < 3; i++) {
            for (int j = 0; j < 3; j++) {
                Rbp[i][j] = (double)g_R[b][i * 3 + j];
                Rbg[i][j] = (double)pose[b * 16 + i * 4 + j];
            }
            tbp[i] = (double)g_t[b][i];
            tbg[i] = (double)pose[b * 16 + i * 4 + 3];
        }
        // rel = inv(T0) @ Tb : Rr = R0^T Rb, tr = R0^T (tb - t0)
        double Rpr[3][3], Rgt[3][3], tpr[3], tgt[3];
        for (int i = 0; i < 3; i++) {
            for (int j = 0; j < 3; j++) {
                Rpr[i][j] = R0p[0][i] * Rbp[0][j] + R0p[1][i] * Rbp[1][j] + R0p[2][i] * Rbp[2][j];
                Rgt[i][j] = R0g[0][i] * Rbg[0][j] + R0g[1][i] * Rbg[1][j] + R0g[2][i] * Rbg[2][j];
            }
            tpr[i] = R0p[0][i] * (tbp[0] - t0p[0]) + R0p[1][i] * (tbp[1] - t0p[1]) + R0p[2][i] * (tbp[2] - t0p[2]);
            tgt[i] = R0g[0][i] * (tbg[0] - t0g[0]) + R0g[1][i] * (tbg[1] - t0g[1]) + R0g[2][i] * (tbg[2] - t0g[2]);
        }
        // trace(Rpr^T Rgt) = elementwise dot
        double trc = 0.0;
        for (int i = 0; i < 3; i++)
            for (int j = 0; j < 3; j++) trc += Rpr[i][j] * Rgt[i][j];
        double cosang = 0.5 * (trc - 1.0);
        if (cosang > hi) cosang = hi;
        if (cosang < lo) cosang = lo;
        rot_sum += acos(cosang);

        const double d0 = tpr[0] - tgt[0], d1 = tpr[1] - tgt[1], d2 = tpr[2] - tgt[2];
        trans_sum += sqrt(d0 * d0 + d1 * d1 + d2 * d2);
    }
    const float rot_loss = (float)(rot_sum / (double)BN);
    const float trans_loss = (float)(trans_sum / (double)BN);
    out[0] = rot_loss + trans_loss;
    out[1] = rot_loss;
    out[2] = trans_loss;
}

extern "C" void kernel_launch(void* const* d_in, const int* in_sizes, int n_in,
                              void* d_out, int out_size) {
    const float* pts  = (const float*)d_in[0];   // (B,H,W,3)
    const float* conf = (const float*)d_in[1];   // (B,H,W)
    const float* Kin  = (const float*)d_in[2];   // (B,3,3)
    const float* pose = (const float*)d_in[3];   // (B,4,4)
    float* out = (float*)d_out;

    init_kernel<<<1, 512>>>();
    dim3 rgrid(BPB, BN);
    for (int it = 0; it < NITER; it++) {
        reduce_kernel<<<rgrid, TPB>>>(pts, conf, Kin);
        solve_kernel<<<1, 32>>>();
    }
    final_kernel<<<1, 32>>>(pose, out);
}